// round 15
// baseline (speedup 1.0000x reference)
#include <cuda_runtime.h>
#include <cuda_fp16.h>
#include <cstdint>

#define D 64
#define NMAX 100000
#define EMAX 1664000
#define TMAX 6272               // max 16-node tiles

// ---------------------------------------------------------------------------
// Device scratch
// ---------------------------------------------------------------------------
__device__ float4  g_hnew4[NMAX * (D / 4)];   // h_new (produced in fused kernel)
__device__ uint2   g_rec[EMAX];               // CSR records: (src, w bits)
__device__ int     g_cnt[NMAX];               // histogram / write cursors
__device__ int     g_off[NMAX + 1];           // CSR row offsets
__device__ int     g_blk[128];                // block totals for scan
__device__ int     g_flag[TMAX];              // per-tile h_new-ready flags
__device__ uint8_t g_Bimg[69632];             // fp16 weight image (grouped cols)
__device__ float   g_biasf[256];              // biases: [r|z|i_n|h_n]
__device__ int     g_is32;                    // src/dst dtype flag

// SMEM map (4 gemm quads per CTA)
#define STRIDE_A 272
#define A_HALF_W 4352
#define A_WARP   8704
#define N_QUAD   4
#define B_IMG    69632
#define SM_BIAS  0
#define SM_A     1024
#define SM_B     (SM_A + N_QUAD * A_WARP)     // 35840
#define SM_TOT   (SM_B + B_IMG)               // 105472

// ---------------------------------------------------------------------------
// Helpers
// ---------------------------------------------------------------------------
__device__ __forceinline__ uint32_t smem_u32(const void* p) {
    uint32_t a;
    asm("{ .reg .u64 t; cvta.to.shared.u64 t, %1; cvt.u32.u64 %0, t; }"
        : "=r"(a) : "l"(p));
    return a;
}
__device__ __forceinline__ uint32_t cvth2(float hi, float lo) {
    uint32_t d;
    asm("cvt.rn.f16x2.f32 %0, %1, %2;" : "=r"(d) : "f"(hi), "f"(lo));
    return d;
}
__device__ __forceinline__ float f16lo_f(uint32_t p) {
    float f; unsigned short s = (unsigned short)(p & 0xffffu);
    asm("cvt.f32.f16 %0, %1;" : "=f"(f) : "h"(s));
    return f;
}
__device__ __forceinline__ float f16hi_f(uint32_t p) { return f16lo_f(p >> 16); }

__device__ __forceinline__ float sigmoidf_fast(float x) {
    return __fdividef(1.0f, 1.0f + __expf(-x));
}
__device__ __forceinline__ float tanhf_fast(float x) {
    return 1.0f - __fdividef(2.0f, __expf(2.0f * x) + 1.0f);
}

#define LDSM4(r0, r1, r2, r3, a)                                            \
    asm volatile("ldmatrix.sync.aligned.m8n8.x4.shared.b16 {%0,%1,%2,%3}, [%4];" \
                 : "=r"(r0), "=r"(r1), "=r"(r2), "=r"(r3) : "r"(a))

#define MMA16816(c, a0, a1, a2, a3, b0, b1)                                 \
    asm volatile("mma.sync.aligned.m16n8k16.row.col.f32.f16.f16.f32 "       \
                 "{%0,%1,%2,%3}, {%4,%5,%6,%7}, {%8,%9}, {%0,%1,%2,%3};"    \
                 : "+f"((c)[0]), "+f"((c)[1]), "+f"((c)[2]), "+f"((c)[3])   \
                 : "r"(a0), "r"(a1), "r"(a2), "r"(a3), "r"(b0), "r"(b1))

#define QUAD_BAR(id) asm volatile("bar.sync %0, 128;" :: "r"(id) : "memory")

__device__ __forceinline__ void flag_set(int t) {
    asm volatile("st.global.release.gpu.u32 [%0], %1;"
                 :: "l"((unsigned long long)(size_t)&g_flag[t]), "r"(1) : "memory");
}
__device__ __forceinline__ void flag_wait(int t) {
    const unsigned long long p = (unsigned long long)(size_t)&g_flag[t];
    uint32_t f;
    asm volatile("ld.global.acquire.gpu.u32 %0, [%1];" : "=r"(f) : "l"(p) : "memory");
    while (!f) {
        __nanosleep(64);
        asm volatile("ld.global.acquire.gpu.u32 %0, [%1];" : "=r"(f) : "l"(p) : "memory");
    }
}

// ---------------------------------------------------------------------------
// zcnt: zero counters + tile flags (+ dtype detection)
// ---------------------------------------------------------------------------
__global__ void zcnt_kernel(const unsigned long long* __restrict__ src,
                            const unsigned long long* __restrict__ dst,
                            int Nn, int n_tiles) {
    int i = blockIdx.x * blockDim.x + threadIdx.x;
    if (i < Nn) g_cnt[i] = 0;
    if (i < n_tiles) g_flag[i] = 0;
    if (i == 0) {
        unsigned long long acc = 0;
#pragma unroll
        for (int k = 0; k < 8; k++) acc |= (src[k] >> 32) | (dst[k] >> 32);
        g_is32 = (acc != 0ULL) ? 1 : 0;
    }
}

__global__ void hist_kernel(const void* __restrict__ dstp, int E) {
    int e = blockIdx.x * blockDim.x + threadIdx.x;
    if (e >= E) return;
    int d = g_is32 ? ((const int*)dstp)[e]
                   : (int)((const long long*)dstp)[e];
    atomicAdd(&g_cnt[d], 1);
}

__global__ void __launch_bounds__(1024) scanA_kernel(int Nn) {
    __shared__ int ws[32];
    const int t = threadIdx.x, lane = t & 31, wid = t >> 5;
    const int i = blockIdx.x * 1024 + t;
    int c = (i < Nn) ? g_cnt[i] : 0;
    int v = c;
#pragma unroll
    for (int d = 1; d < 32; d <<= 1) {
        int n = __shfl_up_sync(0xffffffffu, v, d);
        if (lane >= d) v += n;
    }
    if (lane == 31) ws[wid] = v;
    __syncthreads();
    if (wid == 0) {
        int wv = ws[lane];
#pragma unroll
        for (int d = 1; d < 32; d <<= 1) {
            int n = __shfl_up_sync(0xffffffffu, wv, d);
            if (lane >= d) wv += n;
        }
        ws[lane] = wv;
    }
    __syncthreads();
    int incl = v + (wid ? ws[wid - 1] : 0);
    if (i < Nn) g_off[i] = incl - c;
    if (t == 1023) g_blk[blockIdx.x] = incl;
}

__global__ void __launch_bounds__(256) scanC_kernel(int Nn, int E) {
    __shared__ int ssum[8];
    const int t = threadIdx.x, lane = t & 31, wid = t >> 5;
    const int myblk = blockIdx.x >> 2;
    int v = (t < 128 && t < myblk) ? g_blk[t] : 0;
#pragma unroll
    for (int d = 16; d > 0; d >>= 1) v += __shfl_down_sync(0xffffffffu, v, d);
    if (lane == 0) ssum[wid] = v;
    __syncthreads();
    int blkoff = ssum[0] + ssum[1] + ssum[2] + ssum[3];

    int i = blockIdx.x * 256 + t;
    if (i < Nn) {
        int off = g_off[i] + blkoff;
        g_off[i] = off;
        g_cnt[i] = off;
    }
    if (i == 0) g_off[Nn] = E;
}

__global__ void reorder_kernel(const void* __restrict__ srcp,
                               const void* __restrict__ dstp,
                               const float* __restrict__ ew, int E) {
    int e = blockIdx.x * blockDim.x + threadIdx.x;
    if (e >= E) return;
    int s, d;
    if (g_is32) {
        s = ((const int*)srcp)[e];
        d = ((const int*)dstp)[e];
    } else {
        s = (int)((const long long*)srcp)[e];
        d = (int)((const long long*)dstp)[e];
    }
    int pos = atomicAdd(&g_cnt[d], 1);
    g_rec[pos] = make_uint2((uint32_t)s, __float_as_uint(__ldg(&ew[e])));
}

// ---------------------------------------------------------------------------
// prep — fp16 weight image, GROUPED col order [r|z|i_n|h_n], + biases.
// ---------------------------------------------------------------------------
__global__ void prep_kernel(const float* __restrict__ Wih,
                            const float* __restrict__ Whh,
                            const float* __restrict__ bih,
                            const float* __restrict__ bhh) {
    int idx = blockIdx.x * blockDim.x + threadIdx.x;
    if (idx < 8192) {
        int colp = idx >> 5, q = idx & 31;
        int g = colp >> 6, j = colp & 63;
        int kk = (q & 15) * 4;
        bool isX = (q < 16);
        float4 v = make_float4(0.f, 0.f, 0.f, 0.f);
        const float* srcRow = nullptr;
        if (g == 0)      srcRow = isX ? &Wih[j * 64]         : &Whh[j * 64];
        else if (g == 1) srcRow = isX ? &Wih[(64 + j) * 64]  : &Whh[(64 + j) * 64];
        else if (g == 2) srcRow = isX ? &Wih[(128 + j) * 64] : nullptr;
        else             srcRow = isX ? nullptr              : &Whh[(128 + j) * 64];
        if (srcRow) v = *(const float4*)(srcRow + kk);

        uint32_t h01 = cvth2(v.y, v.x), h23 = cvth2(v.w, v.z);
        uint32_t off = (uint32_t)colp * STRIDE_A + ((q >> 1) << 4) + ((q & 1) << 3);
        *(uint2*)(g_Bimg + off) = make_uint2(h01, h23);
    }
    if (idx < 64) {
        g_biasf[idx]       = bih[idx] + bhh[idx];
        g_biasf[64 + idx]  = bih[64 + idx] + bhh[64 + idx];
        g_biasf[128 + idx] = bih[128 + idx];
        g_biasf[192 + idx] = bhh[128 + idx];
    }
}

// ---------------------------------------------------------------------------
// FUSED persistent kernel: 768 threads; warps 0-15 = 4 gemm quads (consumer),
// warps 16-23 = 8 accum warps (producer). Accum warps build h_new per 16-node
// tile and flag_set(tile); gemm quads flag_wait(tile) then run the R14
// datapath. grid=148 -> all CTAs resident -> spin-wait is deadlock-free.
// ---------------------------------------------------------------------------
__global__ void __launch_bounds__(768, 1)
fused_kernel(const float4* __restrict__ h4, float* __restrict__ out,
             int Nn, int n_tiles16) {
    extern __shared__ __align__(16) char smem[];
    const uint32_t sb = smem_u32(smem);
    const int tid = threadIdx.x;
    const int w = tid >> 5, l = tid & 31;

    // --- B image + bias -> SMEM (all warps) ---
    {
        const uint4* srcB = (const uint4*)g_Bimg;
        uint4* dstB = (uint4*)(smem + SM_B);
        for (int i = tid; i < B_IMG / 16; i += 768) dstB[i] = srcB[i];
        if (tid < 256) ((float*)smem)[tid] = g_biasf[tid];
    }
    __syncthreads();

    if (w >= 16) {
        // =================== PRODUCER: accum warps ===================
        const int aw = blockIdx.x * 8 + (w - 16);      // global accum warp id
        const int stride = gridDim.x * 8;
        const int halfsel = l >> 4, p = l & 15;

        for (int t = aw; t < n_tiles16; t += stride) {
#pragma unroll 1
            for (int ii = 0; ii < 8; ii++) {
                const int node = t * 16 + ii * 2 + halfsel;
                if (node < Nn) {
                    int e = g_off[node];
                    const int end = g_off[node + 1];
                    float4 acc = make_float4(0.f, 0.f, 0.f, 0.f);
                    for (; e + 8 <= end; e += 8) {
                        uint2 r[8];
                        float4 v[8];
#pragma unroll
                        for (int b = 0; b < 8; b++) r[b] = g_rec[e + b];
#pragma unroll
                        for (int b = 0; b < 8; b++)
                            v[b] = __ldg(&h4[(size_t)r[b].x * 16 + p]);
#pragma unroll
                        for (int b = 0; b < 8; b++) {
                            float wv = __uint_as_float(r[b].y);
                            acc.x = fmaf(v[b].x, wv, acc.x);
                            acc.y = fmaf(v[b].y, wv, acc.y);
                            acc.z = fmaf(v[b].z, wv, acc.z);
                            acc.w = fmaf(v[b].w, wv, acc.w);
                        }
                    }
                    for (; e < end; e++) {
                        uint2 r = g_rec[e];
                        float4 v = __ldg(&h4[(size_t)r.x * 16 + p]);
                        float wv = __uint_as_float(r.y);
                        acc.x = fmaf(v.x, wv, acc.x); acc.y = fmaf(v.y, wv, acc.y);
                        acc.z = fmaf(v.z, wv, acc.z); acc.w = fmaf(v.w, wv, acc.w);
                    }
                    g_hnew4[node * 16 + p] = acc;
                }
            }
            __syncwarp();
            __threadfence();
            if (l == 0) flag_set(t);
        }
        return;
    }

    // =================== CONSUMER: gemm quads (R14 datapath) ===================
    const int quad = w >> 2, qpar = w & 3;
    const int t4 = tid & 127;
    const int r0q = l >> 2, tg = l & 3;
    const int barid = quad + 1;

    const int quadA_off = SM_A + quad * A_WARP;
    const int sel = l >> 3;
    const uint32_t a_base = sb + (uint32_t)quadA_off +
        (uint32_t)((((sel & 1) << 3) + (l & 7)) * STRIDE_A + ((sel >> 1) << 4));
    const uint32_t b_base = sb + SM_B + (uint32_t)qpar * (16 * STRIDE_A) +
        (uint32_t)((((sel >> 1) << 3) + (l & 7)) * STRIDE_A + ((sel & 1) << 4));

    for (int tw = blockIdx.x * N_QUAD + quad; tw < n_tiles16;
         tw += gridDim.x * N_QUAD) {
        const int m0 = tw << 4;

        flag_wait(tw);            // h_new tile ready (acquire)

        // --- A tile (16 rows, quad-shared): f32 -> fp16 hi/lo split ---
#pragma unroll
        for (int ii = 0; ii < 4; ii++) {
            int row = ii * 4 + (t4 >> 5);
            int node = m0 + row;
            int kq = t4 & 31;                         // <16: hnew, >=16: h
            float4 v = make_float4(0.f, 0.f, 0.f, 0.f);
            if (node < Nn)
                v = (kq < 16) ? __ldcg(&g_hnew4[node * 16 + kq])
                              : __ldg(&h4[node * 16 + (kq - 16)]);
            uint32_t h01 = cvth2(v.y, v.x), h23 = cvth2(v.w, v.z);
            uint32_t l01 = cvth2(v.y - f16hi_f(h01), v.x - f16lo_f(h01));
            uint32_t l23 = cvth2(v.w - f16hi_f(h23), v.z - f16lo_f(h23));
            uint32_t off = (uint32_t)quadA_off + (uint32_t)row * STRIDE_A +
                           ((uint32_t)(kq >> 1) << 4) + ((uint32_t)(kq & 1) << 3);
            *(uint2*)(smem + off)            = make_uint2(h01, h23);
            *(uint2*)(smem + off + A_HALF_W) = make_uint2(l01, l23);
        }
        QUAD_BAR(barid);

        float acc[32];
#pragma unroll
        for (int i = 0; i < 32; i++) acc[i] = 0.f;

        // ---- fp16 2-pass GEMM; gates g: 0=r 1=z 2=i_n(k<64) 3=h_n(k>=64) ----
#pragma unroll 1
        for (int s = 0; s < 4; s++) {
            uint32_t ah0, ah1, ah2, ah3, al0, al1, al2, al3;
            LDSM4(ah0, ah1, ah2, ah3, a_base + (uint32_t)s * 32);
            LDSM4(al0, al1, al2, al3, a_base + A_HALF_W + (uint32_t)s * 32);
#pragma unroll
            for (int g = 0; g < 3; g++) {             // r, z, i_n
                uint32_t b0, b1, b2, b3;
                LDSM4(b0, b1, b2, b3,
                      b_base + (uint32_t)g * (64 * STRIDE_A) + (uint32_t)s * 32);
                float* c0 = &acc[g * 8];
                float* c1 = &acc[g * 8 + 4];
                MMA16816(c0, ah0, ah1, ah2, ah3, b0, b1);
                MMA16816(c1, ah0, ah1, ah2, ah3, b2, b3);
                MMA16816(c0, al0, al1, al2, al3, b0, b1);
                MMA16816(c1, al0, al1, al2, al3, b2, b3);
            }
        }
#pragma unroll 1
        for (int s = 4; s < 8; s++) {
            uint32_t ah0, ah1, ah2, ah3, al0, al1, al2, al3;
            LDSM4(ah0, ah1, ah2, ah3, a_base + (uint32_t)s * 32);
            LDSM4(al0, al1, al2, al3, a_base + A_HALF_W + (uint32_t)s * 32);
#pragma unroll
            for (int q = 0; q < 3; q++) {
                int g = (q < 2) ? q : 3;              // r, z, h_n
                uint32_t b0, b1, b2, b3;
                LDSM4(b0, b1, b2, b3,
                      b_base + (uint32_t)g * (64 * STRIDE_A) + (uint32_t)s * 32);
                float* c0 = &acc[g * 8];
                float* c1 = &acc[g * 8 + 4];
                MMA16816(c0, ah0, ah1, ah2, ah3, b0, b1);
                MMA16816(c1, ah0, ah1, ah2, ah3, b2, b3);
                MMA16816(c0, al0, al1, al2, al3, b0, b1);
                MMA16816(c1, al0, al1, al2, al3, b2, b3);
            }
        }

        // --- Epilogue phase 1: gate math; j = 16*qpar + 8f + 2tg + b ---
#pragma unroll
        for (int f = 0; f < 2; f++) {
            const int jbase = 16 * qpar + 8 * f + 2 * tg;
            float2 br = *(const float2*)(smem + SM_BIAS + jbase * 4);
            float2 bz = *(const float2*)(smem + SM_BIAS + 256 + jbase * 4);
            float2 bi = *(const float2*)(smem + SM_BIAS + 512 + jbase * 4);
            float2 bh = *(const float2*)(smem + SM_BIAS + 768 + jbase * 4);
#pragma unroll
            for (int rs = 0; rs < 2; rs++) {
                const int node_local = r0q + rs * 8;
#pragma unroll
                for (int b = 0; b < 2; b++) {
                    int j = jbase + b;
                    int ai = f * 4 + 2 * rs + b;
                    float rp = acc[ai];
                    float zp = acc[8 + ai];
                    float ip = acc[16 + ai];
                    float hp = acc[24 + ai];
                    float rr = sigmoidf_fast(rp + (b ? br.y : br.x));
                    float zz = sigmoidf_fast(zp + (b ? bz.y : bz.x));
                    float nn = tanhf_fast(ip + (b ? bi.y : bi.x) +
                                          rr * (hp + (b ? bh.y : bh.x)));
                    int kcol = 64 + j;
                    uint32_t hoff = (uint32_t)quadA_off +
                                    (uint32_t)node_local * STRIDE_A +
                                    ((uint32_t)(kcol >> 3) << 4) +
                                    ((uint32_t)(kcol & 7) << 1);
                    uint32_t hib = *(const unsigned short*)(smem + hoff);
                    uint32_t lob = *(const unsigned short*)(smem + hoff + A_HALF_W);
                    float hv = f16lo_f(hib) + f16lo_f(lob);
                    acc[ai] = (1.f - zz) * nn + zz * hv;
                }
            }
        }
        QUAD_BAR(barid);

        // --- Phase 2: stage float2 into quad staging (XOR swizzle, 8B units) ---
#pragma unroll
        for (int f = 0; f < 2; f++) {
#pragma unroll
            for (int rs = 0; rs < 2; rs++) {
                const int row = r0q + rs * 8;
                uint32_t u8 = (uint32_t)(8 * qpar + 4 * f + tg);
                uint32_t sa = (uint32_t)quadA_off + (uint32_t)row * 256 +
                              ((u8 ^ (((uint32_t)row & 7) << 2)) << 3);
                *(float2*)(smem + sa) =
                    make_float2(acc[f * 4 + 2 * rs], acc[f * 4 + 2 * rs + 1]);
            }
        }
        QUAD_BAR(barid);

        // --- Phase 3: coalesced 16B stores (128 threads x 2 iters) ---
#pragma unroll
        for (int it = 0; it < 2; it++) {
            int idx = it * 128 + t4;
            int nl = idx >> 4, c16 = idx & 15;
            uint32_t ra = (uint32_t)quadA_off + (uint32_t)nl * 256 +
                          ((((uint32_t)(2 * c16)) ^ (((uint32_t)nl & 7) << 2)) << 3);
            float4 v = *(const float4*)(smem + ra);
            int node = m0 + nl;
            if (node < Nn) *(float4*)(out + (size_t)node * 64 + c16 * 4) = v;
        }
        QUAD_BAR(barid);
    }
}

// ---------------------------------------------------------------------------
// Launch
// ---------------------------------------------------------------------------
extern "C" void kernel_launch(void* const* d_in, const int* in_sizes, int n_in,
                              void* d_out, int out_size) {
    const float* h   = (const float*)d_in[0];
    const float* ew  = (const float*)d_in[1];
    const float* Wih = (const float*)d_in[2];
    const float* Whh = (const float*)d_in[3];
    const float* bih = (const float*)d_in[4];
    const float* bhh = (const float*)d_in[5];
    const void* srcp = d_in[6];
    const void* dstp = d_in[7];
    float* out       = (float*)d_out;

    int E  = in_sizes[1];
    int Nn = in_sizes[0] / D;
    int n_tiles16 = (Nn + 15) / 16;
    int eblocks = (E + 255) / 256;
    int nb = (Nn + 1023) / 1024;
    int zmax = (Nn > n_tiles16 ? Nn : n_tiles16);

    zcnt_kernel<<<(zmax + 255) / 256, 256>>>((const unsigned long long*)srcp,
                                             (const unsigned long long*)dstp,
                                             Nn, n_tiles16);
    hist_kernel<<<eblocks, 256>>>(dstp, E);
    scanA_kernel<<<nb, 1024>>>(Nn);
    scanC_kernel<<<(Nn + 255) / 256, 256>>>(Nn, E);
    reorder_kernel<<<eblocks, 256>>>(srcp, dstp, ew, E);

    prep_kernel<<<32, 256>>>(Wih, Whh, bih, bhh);

    cudaFuncSetAttribute(fused_kernel,
                         cudaFuncAttributeMaxDynamicSharedMemorySize, SM_TOT);
    fused_kernel<<<148, 768, SM_TOT>>>((const float4*)h, out, Nn, n_tiles16);
}

// round 16
// speedup vs baseline: 1.5423x; 1.5423x over previous
#include <cuda_runtime.h>
#include <cuda_fp16.h>
#include <cstdint>

#define D 64
#define NMAX 100000
#define EMAX 1664000

// ---------------------------------------------------------------------------
// Device scratch
// ---------------------------------------------------------------------------
__device__ float4  g_hnew4[NMAX * (D / 4)];   // h_new result (25.6 MB)
__device__ uint2   g_h16[NMAX * 16];          // fp16 image of h (12.8 MB)
__device__ uint2   g_rec[EMAX];               // CSR records: (src, w bits)
__device__ int     g_cnt[NMAX];               // histogram / write cursors
__device__ int     g_off[NMAX + 1];           // CSR row offsets
__device__ int     g_blk[128];                // block totals for scan
__device__ uint8_t g_Bimg[69632];             // fp16 weight image (grouped cols)
__device__ float   g_biasf[256];              // biases: [r(64)|z(64)|i_n(64)|h_n(64)]
__device__ int     g_is32;                    // src/dst dtype flag

// SMEM map for the GEMM kernel (per-QUAD A regions; 6 quads / 768-thread CTA)
#define STRIDE_A 272
#define A_HALF_W 4352
#define A_WARP   8704
#define N_QUAD   6
#define B_IMG    69632
#define SM_BIAS  0
#define SM_A     1024
#define SM_B     (SM_A + N_QUAD * A_WARP)     // 53248
#define SM_TOT   (SM_B + B_IMG)               // 122880

// ---------------------------------------------------------------------------
// Helpers
// ---------------------------------------------------------------------------
__device__ __forceinline__ uint32_t smem_u32(const void* p) {
    uint32_t a;
    asm("{ .reg .u64 t; cvta.to.shared.u64 t, %1; cvt.u32.u64 %0, t; }"
        : "=r"(a) : "l"(p));
    return a;
}
__device__ __forceinline__ uint32_t cvth2(float hi, float lo) {
    uint32_t d;
    asm("cvt.rn.f16x2.f32 %0, %1, %2;" : "=r"(d) : "f"(hi), "f"(lo));
    return d;
}
__device__ __forceinline__ float f16lo_f(uint32_t p) {
    float f; unsigned short s = (unsigned short)(p & 0xffffu);
    asm("cvt.f32.f16 %0, %1;" : "=f"(f) : "h"(s));
    return f;
}
__device__ __forceinline__ float f16hi_f(uint32_t p) { return f16lo_f(p >> 16); }

__device__ __forceinline__ float sigmoidf_fast(float x) {
    return __fdividef(1.0f, 1.0f + __expf(-x));
}
__device__ __forceinline__ float tanhf_fast(float x) {
    return 1.0f - __fdividef(2.0f, __expf(2.0f * x) + 1.0f);
}

#define LDSM4(r0, r1, r2, r3, a)                                            \
    asm volatile("ldmatrix.sync.aligned.m8n8.x4.shared.b16 {%0,%1,%2,%3}, [%4];" \
                 : "=r"(r0), "=r"(r1), "=r"(r2), "=r"(r3) : "r"(a))

#define MMA16816(c, a0, a1, a2, a3, b0, b1)                                 \
    asm volatile("mma.sync.aligned.m16n8k16.row.col.f32.f16.f16.f32 "       \
                 "{%0,%1,%2,%3}, {%4,%5,%6,%7}, {%8,%9}, {%0,%1,%2,%3};"    \
                 : "+f"((c)[0]), "+f"((c)[1]), "+f"((c)[2]), "+f"((c)[3])   \
                 : "r"(a0), "r"(a1), "r"(a2), "r"(a3), "r"(b0), "r"(b1))

#define QUAD_BAR(id) asm volatile("bar.sync %0, 128;" :: "r"(id) : "memory")

// ---------------------------------------------------------------------------
// zcnt (+ fused index-dtype detection in block 0)
// ---------------------------------------------------------------------------
__global__ void zcnt_kernel(const unsigned long long* __restrict__ src,
                            const unsigned long long* __restrict__ dst, int Nn) {
    int i = blockIdx.x * blockDim.x + threadIdx.x;
    if (i < Nn) g_cnt[i] = 0;
    if (i == 0) {
        unsigned long long acc = 0;
#pragma unroll
        for (int k = 0; k < 8; k++) acc |= (src[k] >> 32) | (dst[k] >> 32);
        g_is32 = (acc != 0ULL) ? 1 : 0;
    }
}

// hist + fp16 h-image conversion (grid spans max(E, Nn*16))
__global__ void hist_kernel(const void* __restrict__ dstp,
                            const float4* __restrict__ h4,
                            int E, int nquads) {
    int e = blockIdx.x * blockDim.x + threadIdx.x;
    if (e < nquads) {
        float4 v = __ldg(&h4[e]);
        g_h16[e] = make_uint2(cvth2(v.y, v.x), cvth2(v.w, v.z));
    }
    if (e >= E) return;
    int d = g_is32 ? ((const int*)dstp)[e]
                   : (int)((const long long*)dstp)[e];
    atomicAdd(&g_cnt[d], 1);
}

// Hierarchical scan A: 1024-wide block scan; g_off = within-block exclusive.
__global__ void __launch_bounds__(1024) scanA_kernel(int Nn) {
    __shared__ int ws[32];
    const int t = threadIdx.x, lane = t & 31, wid = t >> 5;
    const int i = blockIdx.x * 1024 + t;
    int c = (i < Nn) ? g_cnt[i] : 0;
    int v = c;
#pragma unroll
    for (int d = 1; d < 32; d <<= 1) {
        int n = __shfl_up_sync(0xffffffffu, v, d);
        if (lane >= d) v += n;
    }
    if (lane == 31) ws[wid] = v;
    __syncthreads();
    if (wid == 0) {
        int wv = ws[lane];
#pragma unroll
        for (int d = 1; d < 32; d <<= 1) {
            int n = __shfl_up_sync(0xffffffffu, wv, d);
            if (lane >= d) wv += n;
        }
        ws[lane] = wv;
    }
    __syncthreads();
    int incl = v + (wid ? ws[wid - 1] : 0);
    if (i < Nn) g_off[i] = incl - c;
    if (t == 1023) g_blk[blockIdx.x] = incl;
}

// scanC with block-offset reduction folded in.
__global__ void __launch_bounds__(256) scanC_kernel(int Nn, int E) {
    __shared__ int ssum[8];
    const int t = threadIdx.x, lane = t & 31, wid = t >> 5;
    const int myblk = blockIdx.x >> 2;
    int v = (t < 128 && t < myblk) ? g_blk[t] : 0;
#pragma unroll
    for (int d = 16; d > 0; d >>= 1) v += __shfl_down_sync(0xffffffffu, v, d);
    if (lane == 0) ssum[wid] = v;
    __syncthreads();
    int blkoff = ssum[0] + ssum[1] + ssum[2] + ssum[3];

    int i = blockIdx.x * 256 + t;
    if (i < Nn) {
        int off = g_off[i] + blkoff;
        g_off[i] = off;
        g_cnt[i] = off;
    }
    if (i == 0) g_off[Nn] = E;
}

__global__ void reorder_kernel(const void* __restrict__ srcp,
                               const void* __restrict__ dstp,
                               const float* __restrict__ ew, int E) {
    int e = blockIdx.x * blockDim.x + threadIdx.x;
    if (e >= E) return;
    int s, d;
    if (g_is32) {
        s = ((const int*)srcp)[e];
        d = ((const int*)dstp)[e];
    } else {
        s = (int)((const long long*)srcp)[e];
        d = (int)((const long long*)dstp)[e];
    }
    int pos = atomicAdd(&g_cnt[d], 1);
    g_rec[pos] = make_uint2((uint32_t)s, __float_as_uint(__ldg(&ew[e])));
}

// ---------------------------------------------------------------------------
// Accumulate: half-warp per node, lane owns a 4-float part; gathers the fp16
// h-image (8B per lane per edge -> half the L2 traffic); fp32 accumulate.
// ---------------------------------------------------------------------------
__global__ void __launch_bounds__(256) accum_kernel(int Nn) {
    int gid = blockIdx.x * blockDim.x + threadIdx.x;
    int node = gid >> 4, p = gid & 15;
    if (node >= Nn) return;
    int e = g_off[node];
    const int end = g_off[node + 1];
    float4 acc = make_float4(0.f, 0.f, 0.f, 0.f);

    for (; e + 4 <= end; e += 4) {
        uint2 r0 = g_rec[e],     r1 = g_rec[e + 1];
        uint2 r2 = g_rec[e + 2], r3 = g_rec[e + 3];
        uint2 q0 = __ldg(&g_h16[(size_t)r0.x * 16 + p]);
        uint2 q1 = __ldg(&g_h16[(size_t)r1.x * 16 + p]);
        uint2 q2 = __ldg(&g_h16[(size_t)r2.x * 16 + p]);
        uint2 q3 = __ldg(&g_h16[(size_t)r3.x * 16 + p]);
        float w0 = __uint_as_float(r0.y), w1 = __uint_as_float(r1.y);
        float w2 = __uint_as_float(r2.y), w3 = __uint_as_float(r3.y);
        acc.x = fmaf(f16lo_f(q0.x), w0, acc.x); acc.y = fmaf(f16hi_f(q0.x), w0, acc.y);
        acc.z = fmaf(f16lo_f(q0.y), w0, acc.z); acc.w = fmaf(f16hi_f(q0.y), w0, acc.w);
        acc.x = fmaf(f16lo_f(q1.x), w1, acc.x); acc.y = fmaf(f16hi_f(q1.x), w1, acc.y);
        acc.z = fmaf(f16lo_f(q1.y), w1, acc.z); acc.w = fmaf(f16hi_f(q1.y), w1, acc.w);
        acc.x = fmaf(f16lo_f(q2.x), w2, acc.x); acc.y = fmaf(f16hi_f(q2.x), w2, acc.y);
        acc.z = fmaf(f16lo_f(q2.y), w2, acc.z); acc.w = fmaf(f16hi_f(q2.y), w2, acc.w);
        acc.x = fmaf(f16lo_f(q3.x), w3, acc.x); acc.y = fmaf(f16hi_f(q3.x), w3, acc.y);
        acc.z = fmaf(f16lo_f(q3.y), w3, acc.z); acc.w = fmaf(f16hi_f(q3.y), w3, acc.w);
    }
    for (; e < end; e++) {
        uint2 r = g_rec[e];
        uint2 q = __ldg(&g_h16[(size_t)r.x * 16 + p]);
        float w = __uint_as_float(r.y);
        acc.x = fmaf(f16lo_f(q.x), w, acc.x); acc.y = fmaf(f16hi_f(q.x), w, acc.y);
        acc.z = fmaf(f16lo_f(q.y), w, acc.z); acc.w = fmaf(f16hi_f(q.y), w, acc.w);
    }
    g_hnew4[node * 16 + p] = acc;
}

// ---------------------------------------------------------------------------
// prep — fp16 weight image, GROUPED col order [r|z|i_n|h_n], + biases.
// ---------------------------------------------------------------------------
__global__ void prep_kernel(const float* __restrict__ Wih,
                            const float* __restrict__ Whh,
                            const float* __restrict__ bih,
                            const float* __restrict__ bhh) {
    int idx = blockIdx.x * blockDim.x + threadIdx.x;
    if (idx < 8192) {
        int colp = idx >> 5, q = idx & 31;
        int g = colp >> 6, j = colp & 63;
        int kk = (q & 15) * 4;
        bool isX = (q < 16);
        float4 v = make_float4(0.f, 0.f, 0.f, 0.f);
        const float* srcRow = nullptr;
        if (g == 0)      srcRow = isX ? &Wih[j * 64]         : &Whh[j * 64];
        else if (g == 1) srcRow = isX ? &Wih[(64 + j) * 64]  : &Whh[(64 + j) * 64];
        else if (g == 2) srcRow = isX ? &Wih[(128 + j) * 64] : nullptr;
        else             srcRow = isX ? nullptr              : &Whh[(128 + j) * 64];
        if (srcRow) v = *(const float4*)(srcRow + kk);

        uint32_t h01 = cvth2(v.y, v.x), h23 = cvth2(v.w, v.z);
        uint32_t off = (uint32_t)colp * STRIDE_A + ((q >> 1) << 4) + ((q & 1) << 3);
        *(uint2*)(g_Bimg + off) = make_uint2(h01, h23);
    }
    if (idx < 64) {
        g_biasf[idx]       = bih[idx] + bhh[idx];
        g_biasf[64 + idx]  = bih[64 + idx] + bhh[64 + idx];
        g_biasf[128 + idx] = bih[128 + idx];
        g_biasf[192 + idx] = bhh[128 + idx];
    }
}

// ---------------------------------------------------------------------------
// GEMM + GRU epilogue: 768 threads (24 warps = 6 QUADS) per CTA (R14 proven).
// ---------------------------------------------------------------------------
__global__ void __launch_bounds__(768, 1)
gemm_gru_kernel(const float4* __restrict__ h4, float* __restrict__ out,
                int Nn, int n_tiles16) {
    extern __shared__ __align__(16) char smem[];
    const uint32_t sb = smem_u32(smem);
    const int tid = threadIdx.x;
    const int w = tid >> 5, l = tid & 31;
    const int quad = w >> 2, qpar = w & 3;
    const int t4 = tid & 127;
    const int r0q = l >> 2, tg = l & 3;
    const int barid = quad + 1;

    // --- B image + bias -> SMEM ---
    {
        const uint4* srcB = (const uint4*)g_Bimg;
        uint4* dstB = (uint4*)(smem + SM_B);
        for (int i = tid; i < B_IMG / 16; i += 768) dstB[i] = srcB[i];
        if (tid < 256) ((float*)smem)[tid] = g_biasf[tid];
    }
    __syncthreads();

    const int quadA_off = SM_A + quad * A_WARP;
    const int sel = l >> 3;
    const uint32_t a_base = sb + (uint32_t)quadA_off +
        (uint32_t)((((sel & 1) << 3) + (l & 7)) * STRIDE_A + ((sel >> 1) << 4));
    const uint32_t b_base = sb + SM_B + (uint32_t)qpar * (16 * STRIDE_A) +
        (uint32_t)((((sel >> 1) << 3) + (l & 7)) * STRIDE_A + ((sel & 1) << 4));

    for (int tw = blockIdx.x * N_QUAD + quad; tw < n_tiles16;
         tw += gridDim.x * N_QUAD) {
        const int m0 = tw << 4;

        // --- A tile (16 rows, quad-shared): f32 -> fp16 hi/lo split ---
#pragma unroll
        for (int ii = 0; ii < 4; ii++) {
            int row = ii * 4 + (t4 >> 5);
            int node = m0 + row;
            int kq = t4 & 31;                         // <16: hnew, >=16: h
            float4 v = make_float4(0.f, 0.f, 0.f, 0.f);
            if (node < Nn)
                v = (kq < 16) ? g_hnew4[node * 16 + kq]
                              : __ldg(&h4[node * 16 + (kq - 16)]);
            uint32_t h01 = cvth2(v.y, v.x), h23 = cvth2(v.w, v.z);
            uint32_t l01 = cvth2(v.y - f16hi_f(h01), v.x - f16lo_f(h01));
            uint32_t l23 = cvth2(v.w - f16hi_f(h23), v.z - f16lo_f(h23));
            uint32_t off = (uint32_t)quadA_off + (uint32_t)row * STRIDE_A +
                           ((uint32_t)(kq >> 1) << 4) + ((uint32_t)(kq & 1) << 3);
            *(uint2*)(smem + off)            = make_uint2(h01, h23);
            *(uint2*)(smem + off + A_HALF_W) = make_uint2(l01, l23);
        }
        QUAD_BAR(barid);

        float acc[32];
#pragma unroll
        for (int i = 0; i < 32; i++) acc[i] = 0.f;

        // ---- fp16 2-pass GEMM; gates g: 0=r 1=z 2=i_n(k<64) 3=h_n(k>=64) ----
#pragma unroll 1
        for (int s = 0; s < 4; s++) {
            uint32_t ah0, ah1, ah2, ah3, al0, al1, al2, al3;
            LDSM4(ah0, ah1, ah2, ah3, a_base + (uint32_t)s * 32);
            LDSM4(al0, al1, al2, al3, a_base + A_HALF_W + (uint32_t)s * 32);
#pragma unroll
            for (int g = 0; g < 3; g++) {             // r, z, i_n
                uint32_t b0, b1, b2, b3;
                LDSM4(b0, b1, b2, b3,
                      b_base + (uint32_t)g * (64 * STRIDE_A) + (uint32_t)s * 32);
                float* c0 = &acc[g * 8];
                float* c1 = &acc[g * 8 + 4];
                MMA16816(c0, ah0, ah1, ah2, ah3, b0, b1);
                MMA16816(c1, ah0, ah1, ah2, ah3, b2, b3);
                MMA16816(c0, al0, al1, al2, al3, b0, b1);
                MMA16816(c1, al0, al1, al2, al3, b2, b3);
            }
        }
#pragma unroll 1
        for (int s = 4; s < 8; s++) {
            uint32_t ah0, ah1, ah2, ah3, al0, al1, al2, al3;
            LDSM4(ah0, ah1, ah2, ah3, a_base + (uint32_t)s * 32);
            LDSM4(al0, al1, al2, al3, a_base + A_HALF_W + (uint32_t)s * 32);
#pragma unroll
            for (int q = 0; q < 3; q++) {
                int g = (q < 2) ? q : 3;              // r, z, h_n
                uint32_t b0, b1, b2, b3;
                LDSM4(b0, b1, b2, b3,
                      b_base + (uint32_t)g * (64 * STRIDE_A) + (uint32_t)s * 32);
                float* c0 = &acc[g * 8];
                float* c1 = &acc[g * 8 + 4];
                MMA16816(c0, ah0, ah1, ah2, ah3, b0, b1);
                MMA16816(c1, ah0, ah1, ah2, ah3, b2, b3);
                MMA16816(c0, al0, al1, al2, al3, b0, b1);
                MMA16816(c1, al0, al1, al2, al3, b2, b3);
            }
        }

        // --- Epilogue phase 1: gate math; j = 16*qpar + 8f + 2tg + b ---
#pragma unroll
        for (int f = 0; f < 2; f++) {
            const int jbase = 16 * qpar + 8 * f + 2 * tg;
            float2 br = *(const float2*)(smem + SM_BIAS + jbase * 4);
            float2 bz = *(const float2*)(smem + SM_BIAS + 256 + jbase * 4);
            float2 bi = *(const float2*)(smem + SM_BIAS + 512 + jbase * 4);
            float2 bh = *(const float2*)(smem + SM_BIAS + 768 + jbase * 4);
#pragma unroll
            for (int rs = 0; rs < 2; rs++) {
                const int node_local = r0q + rs * 8;
#pragma unroll
                for (int b = 0; b < 2; b++) {
                    int j = jbase + b;
                    int ai = f * 4 + 2 * rs + b;
                    float rp = acc[ai];
                    float zp = acc[8 + ai];
                    float ip = acc[16 + ai];
                    float hp = acc[24 + ai];
                    float rr = sigmoidf_fast(rp + (b ? br.y : br.x));
                    float zz = sigmoidf_fast(zp + (b ? bz.y : bz.x));
                    float nn = tanhf_fast(ip + (b ? bi.y : bi.x) +
                                          rr * (hp + (b ? bh.y : bh.x)));
                    int kcol = 64 + j;
                    uint32_t hoff = (uint32_t)quadA_off +
                                    (uint32_t)node_local * STRIDE_A +
                                    ((uint32_t)(kcol >> 3) << 4) +
                                    ((uint32_t)(kcol & 7) << 1);
                    uint32_t hib = *(const unsigned short*)(smem + hoff);
                    uint32_t lob = *(const unsigned short*)(smem + hoff + A_HALF_W);
                    float hv = f16lo_f(hib) + f16lo_f(lob);
                    acc[ai] = (1.f - zz) * nn + zz * hv;
                }
            }
        }
        QUAD_BAR(barid);

        // --- Phase 2: stage float2 into quad staging (XOR swizzle, 8B units) ---
#pragma unroll
        for (int f = 0; f < 2; f++) {
#pragma unroll
            for (int rs = 0; rs < 2; rs++) {
                const int row = r0q + rs * 8;
                uint32_t u8 = (uint32_t)(8 * qpar + 4 * f + tg);
                uint32_t sa = (uint32_t)quadA_off + (uint32_t)row * 256 +
                              ((u8 ^ (((uint32_t)row & 7) << 2)) << 3);
                *(float2*)(smem + sa) =
                    make_float2(acc[f * 4 + 2 * rs], acc[f * 4 + 2 * rs + 1]);
            }
        }
        QUAD_BAR(barid);

        // --- Phase 3: coalesced 16B stores (128 threads x 2 iters) ---
#pragma unroll
        for (int it = 0; it < 2; it++) {
            int idx = it * 128 + t4;
            int nl = idx >> 4, c16 = idx & 15;
            uint32_t ra = (uint32_t)quadA_off + (uint32_t)nl * 256 +
                          ((((uint32_t)(2 * c16)) ^ (((uint32_t)nl & 7) << 2)) << 3);
            float4 v = *(const float4*)(smem + ra);
            int node = m0 + nl;
            if (node < Nn) *(float4*)(out + (size_t)node * 64 + c16 * 4) = v;
        }
        QUAD_BAR(barid);
    }
}

// ---------------------------------------------------------------------------
// Launch
// ---------------------------------------------------------------------------
extern "C" void kernel_launch(void* const* d_in, const int* in_sizes, int n_in,
                              void* d_out, int out_size) {
    const float* h   = (const float*)d_in[0];
    const float* ew  = (const float*)d_in[1];
    const float* Wih = (const float*)d_in[2];
    const float* Whh = (const float*)d_in[3];
    const float* bih = (const float*)d_in[4];
    const float* bhh = (const float*)d_in[5];
    const void* srcp = d_in[6];
    const void* dstp = d_in[7];
    float* out       = (float*)d_out;

    int E  = in_sizes[1];
    int Nn = in_sizes[0] / D;
    int n_tiles16 = (Nn + 15) / 16;
    int nquads = Nn * 16;
    int hmax = (E > nquads ? E : nquads);
    int nb = (Nn + 1023) / 1024;

    zcnt_kernel<<<(Nn + 255) / 256, 256>>>((const unsigned long long*)srcp,
                                           (const unsigned long long*)dstp, Nn);
    hist_kernel<<<(hmax + 255) / 256, 256>>>(dstp, (const float4*)h, E, nquads);
    scanA_kernel<<<nb, 1024>>>(Nn);
    scanC_kernel<<<(Nn + 255) / 256, 256>>>(Nn, E);
    reorder_kernel<<<(E + 255) / 256, 256>>>(srcp, dstp, ew, E);

    prep_kernel<<<32, 256>>>(Wih, Whh, bih, bhh);

    accum_kernel<<<(Nn * 16 + 255) / 256, 256>>>(Nn);

    cudaFuncSetAttribute(gemm_gru_kernel,
                         cudaFuncAttributeMaxDynamicSharedMemorySize, SM_TOT);
    gemm_gru_kernel<<<148, 768, SM_TOT>>>((const float4*)h, out, Nn, n_tiles16);
}

// round 17
// speedup vs baseline: 1.5856x; 1.0281x over previous
#include <cuda_runtime.h>
#include <cuda_fp16.h>
#include <cstdint>

#define D 64
#define NMAX 100000
#define EMAX 1664000

// ---------------------------------------------------------------------------
// Device scratch
// ---------------------------------------------------------------------------
__device__ float4  g_hnew4[NMAX * (D / 4)];   // h_new result (25.6 MB)
__device__ uint2   g_rec[EMAX];               // CSR records: (src, w bits)
__device__ int     g_cnt[NMAX];               // histogram / write cursors
__device__ int     g_off[NMAX + 1];           // CSR row offsets
__device__ int     g_blk[128];                // block totals for scan
__device__ int     g_done;                    // scan device-sync counter
__device__ uint8_t g_Bimg[69632];             // fp16 weight image (grouped cols)
__device__ float   g_biasf[256];              // biases: [r(64)|z(64)|i_n(64)|h_n(64)]
__device__ int     g_is32;                    // src/dst dtype flag

// SMEM map for the GEMM kernel (per-QUAD A regions; 6 quads / 768-thread CTA)
#define STRIDE_A 272
#define A_HALF_W 4352
#define A_WARP   8704
#define N_QUAD   6
#define B_IMG    69632
#define SM_BIAS  0
#define SM_A     1024
#define SM_B     (SM_A + N_QUAD * A_WARP)     // 53248
#define SM_TOT   (SM_B + B_IMG)               // 122880

// ---------------------------------------------------------------------------
// Helpers
// ---------------------------------------------------------------------------
__device__ __forceinline__ uint32_t smem_u32(const void* p) {
    uint32_t a;
    asm("{ .reg .u64 t; cvta.to.shared.u64 t, %1; cvt.u32.u64 %0, t; }"
        : "=r"(a) : "l"(p));
    return a;
}
__device__ __forceinline__ uint32_t cvth2(float hi, float lo) {
    uint32_t d;
    asm("cvt.rn.f16x2.f32 %0, %1, %2;" : "=r"(d) : "f"(hi), "f"(lo));
    return d;
}
__device__ __forceinline__ float f16lo_f(uint32_t p) {
    float f; unsigned short s = (unsigned short)(p & 0xffffu);
    asm("cvt.f32.f16 %0, %1;" : "=f"(f) : "h"(s));
    return f;
}
__device__ __forceinline__ float f16hi_f(uint32_t p) { return f16lo_f(p >> 16); }

__device__ __forceinline__ float sigmoidf_fast(float x) {
    return __fdividef(1.0f, 1.0f + __expf(-x));
}
__device__ __forceinline__ float tanhf_fast(float x) {
    return 1.0f - __fdividef(2.0f, __expf(2.0f * x) + 1.0f);
}

#define LDSM4(r0, r1, r2, r3, a)                                            \
    asm volatile("ldmatrix.sync.aligned.m8n8.x4.shared.b16 {%0,%1,%2,%3}, [%4];" \
                 : "=r"(r0), "=r"(r1), "=r"(r2), "=r"(r3) : "r"(a))

#define MMA16816(c, a0, a1, a2, a3, b0, b1)                                 \
    asm volatile("mma.sync.aligned.m16n8k16.row.col.f32.f16.f16.f32 "       \
                 "{%0,%1,%2,%3}, {%4,%5,%6,%7}, {%8,%9}, {%0,%1,%2,%3};"    \
                 : "+f"((c)[0]), "+f"((c)[1]), "+f"((c)[2]), "+f"((c)[3])   \
                 : "r"(a0), "r"(a1), "r"(a2), "r"(a3), "r"(b0), "r"(b1))

#define QUAD_BAR(id) asm volatile("bar.sync %0, 128;" :: "r"(id) : "memory")

// ---------------------------------------------------------------------------
// init: zero counters + scan sync counter + dtype detect + weight prep + bias
// (fuses the old zcnt_kernel and prep_kernel — all independent work)
// ---------------------------------------------------------------------------
__global__ void init_kernel(const unsigned long long* __restrict__ src,
                            const unsigned long long* __restrict__ dst,
                            const float* __restrict__ Wih,
                            const float* __restrict__ Whh,
                            const float* __restrict__ bih,
                            const float* __restrict__ bhh, int Nn) {
    int i = blockIdx.x * blockDim.x + threadIdx.x;
    if (i < Nn) g_cnt[i] = 0;
    if (i == 0) {
        g_done = 0;
        unsigned long long acc = 0;
#pragma unroll
        for (int k = 0; k < 8; k++) acc |= (src[k] >> 32) | (dst[k] >> 32);
        g_is32 = (acc != 0ULL) ? 1 : 0;
    }
    if (i < 8192) {
        int colp = i >> 5, q = i & 31;
        int g = colp >> 6, j = colp & 63;
        int kk = (q & 15) * 4;
        bool isX = (q < 16);
        float4 v = make_float4(0.f, 0.f, 0.f, 0.f);
        const float* srcRow = nullptr;
        if (g == 0)      srcRow = isX ? &Wih[j * 64]         : &Whh[j * 64];
        else if (g == 1) srcRow = isX ? &Wih[(64 + j) * 64]  : &Whh[(64 + j) * 64];
        else if (g == 2) srcRow = isX ? &Wih[(128 + j) * 64] : nullptr;
        else             srcRow = isX ? nullptr              : &Whh[(128 + j) * 64];
        if (srcRow) v = *(const float4*)(srcRow + kk);

        uint32_t h01 = cvth2(v.y, v.x), h23 = cvth2(v.w, v.z);
        uint32_t off = (uint32_t)colp * STRIDE_A + ((q >> 1) << 4) + ((q & 1) << 3);
        *(uint2*)(g_Bimg + off) = make_uint2(h01, h23);
    }
    if (i < 64) {
        g_biasf[i]       = bih[i] + bhh[i];
        g_biasf[64 + i]  = bih[64 + i] + bhh[64 + i];
        g_biasf[128 + i] = bih[128 + i];
        g_biasf[192 + i] = bhh[128 + i];
    }
}

__global__ void hist_kernel(const void* __restrict__ dstp, int E) {
    int e = blockIdx.x * blockDim.x + threadIdx.x;
    if (e >= E) return;
    int d = g_is32 ? ((const int*)dstp)[e]
                   : (int)((const long long*)dstp)[e];
    atomicAdd(&g_cnt[d], 1);
}

// ---------------------------------------------------------------------------
// Fused scan: block-scan + publish totals + device-wide sync + add prefix.
// nb <= 128 blocks, all resident (148 SMs) -> spin is deadlock-free.
// ---------------------------------------------------------------------------
__global__ void __launch_bounds__(1024) scan_kernel(int Nn, int E, int nb) {
    __shared__ int ws[32];
    __shared__ int s_blkoff;
    const int t = threadIdx.x, lane = t & 31, wid = t >> 5;
    const int i = blockIdx.x * 1024 + t;
    const int c = (i < Nn) ? g_cnt[i] : 0;
    int v = c;
#pragma unroll
    for (int d = 1; d < 32; d <<= 1) {
        int n = __shfl_up_sync(0xffffffffu, v, d);
        if (lane >= d) v += n;
    }
    if (lane == 31) ws[wid] = v;
    __syncthreads();
    if (wid == 0) {
        int wv = ws[lane];
#pragma unroll
        for (int d = 1; d < 32; d <<= 1) {
            int n = __shfl_up_sync(0xffffffffu, wv, d);
            if (lane >= d) wv += n;
        }
        ws[lane] = wv;
    }
    __syncthreads();
    const int incl = v + (wid ? ws[wid - 1] : 0);
    const int local_off = incl - c;

    // publish block total, then device-wide sync
    if (t == 1023) {
        g_blk[blockIdx.x] = incl;      // block total (incl of last thread)
        __threadfence();
        atomicAdd(&g_done, 1);
    }
    __syncthreads();
    if (t == 0) {
        while (atomicAdd(&g_done, 0) < nb) __nanosleep(128);
    }
    __syncthreads();
    __threadfence();                    // acquire g_blk values

    // blkoff = sum of preceding block totals (warp 0 reduces <=128 values)
    if (wid == 0) {
        int s = 0;
#pragma unroll
        for (int k = 0; k < 4; k++) {
            int idx = k * 32 + lane;
            if (idx < blockIdx.x) s += g_blk[idx];
        }
#pragma unroll
        for (int d = 16; d > 0; d >>= 1) s += __shfl_down_sync(0xffffffffu, s, d);
        if (lane == 0) s_blkoff = s;
    }
    __syncthreads();
    const int blkoff = s_blkoff;

    if (i < Nn) {
        int off = local_off + blkoff;
        g_off[i] = off;
        g_cnt[i] = off;                 // reorder cursor
    }
    if (i == 0) g_off[Nn] = E;
}

__global__ void reorder_kernel(const void* __restrict__ srcp,
                               const void* __restrict__ dstp,
                               const float* __restrict__ ew, int E) {
    int e = blockIdx.x * blockDim.x + threadIdx.x;
    if (e >= E) return;
    int s, d;
    if (g_is32) {
        s = ((const int*)srcp)[e];
        d = ((const int*)dstp)[e];
    } else {
        s = (int)((const long long*)srcp)[e];
        d = (int)((const long long*)dstp)[e];
    }
    int pos = atomicAdd(&g_cnt[d], 1);
    g_rec[pos] = make_uint2((uint32_t)s, __float_as_uint(__ldg(&ew[e])));
}

// ---------------------------------------------------------------------------
// Accumulate (R14 fp32 form): half-warp per node, lane owns one float4 part.
// ---------------------------------------------------------------------------
__global__ void __launch_bounds__(256) accum_kernel(const float4* __restrict__ h4,
                                                    int Nn) {
    int gid = blockIdx.x * blockDim.x + threadIdx.x;
    int node = gid >> 4, p = gid & 15;
    if (node >= Nn) return;
    int e = g_off[node];
    const int end = g_off[node + 1];
    float4 acc = make_float4(0.f, 0.f, 0.f, 0.f);

    for (; e + 4 <= end; e += 4) {
        uint2 r0 = g_rec[e],     r1 = g_rec[e + 1];
        uint2 r2 = g_rec[e + 2], r3 = g_rec[e + 3];
        float4 v0 = __ldg(&h4[(size_t)r0.x * 16 + p]);
        float4 v1 = __ldg(&h4[(size_t)r1.x * 16 + p]);
        float4 v2 = __ldg(&h4[(size_t)r2.x * 16 + p]);
        float4 v3 = __ldg(&h4[(size_t)r3.x * 16 + p]);
        float w0 = __uint_as_float(r0.y), w1 = __uint_as_float(r1.y);
        float w2 = __uint_as_float(r2.y), w3 = __uint_as_float(r3.y);
        acc.x = fmaf(v0.x, w0, acc.x); acc.y = fmaf(v0.y, w0, acc.y);
        acc.z = fmaf(v0.z, w0, acc.z); acc.w = fmaf(v0.w, w0, acc.w);
        acc.x = fmaf(v1.x, w1, acc.x); acc.y = fmaf(v1.y, w1, acc.y);
        acc.z = fmaf(v1.z, w1, acc.z); acc.w = fmaf(v1.w, w1, acc.w);
        acc.x = fmaf(v2.x, w2, acc.x); acc.y = fmaf(v2.y, w2, acc.y);
        acc.z = fmaf(v2.z, w2, acc.z); acc.w = fmaf(v2.w, w2, acc.w);
        acc.x = fmaf(v3.x, w3, acc.x); acc.y = fmaf(v3.y, w3, acc.y);
        acc.z = fmaf(v3.z, w3, acc.z); acc.w = fmaf(v3.w, w3, acc.w);
    }
    for (; e < end; e++) {
        uint2 r = g_rec[e];
        float4 v = __ldg(&h4[(size_t)r.x * 16 + p]);
        float w = __uint_as_float(r.y);
        acc.x = fmaf(v.x, w, acc.x); acc.y = fmaf(v.y, w, acc.y);
        acc.z = fmaf(v.z, w, acc.z); acc.w = fmaf(v.w, w, acc.w);
    }
    g_hnew4[node * 16 + p] = acc;
}

// ---------------------------------------------------------------------------
// GEMM + GRU epilogue: 768 threads (24 warps = 6 QUADS) per CTA (R14 proven).
// ---------------------------------------------------------------------------
__global__ void __launch_bounds__(768, 1)
gemm_gru_kernel(const float4* __restrict__ h4, float* __restrict__ out,
                int Nn, int n_tiles16) {
    extern __shared__ __align__(16) char smem[];
    const uint32_t sb = smem_u32(smem);
    const int tid = threadIdx.x;
    const int w = tid >> 5, l = tid & 31;
    const int quad = w >> 2, qpar = w & 3;
    const int t4 = tid & 127;
    const int r0q = l >> 2, tg = l & 3;
    const int barid = quad + 1;

    // --- B image + bias -> SMEM ---
    {
        const uint4* srcB = (const uint4*)g_Bimg;
        uint4* dstB = (uint4*)(smem + SM_B);
        for (int i = tid; i < B_IMG / 16; i += 768) dstB[i] = srcB[i];
        if (tid < 256) ((float*)smem)[tid] = g_biasf[tid];
    }
    __syncthreads();

    const int quadA_off = SM_A + quad * A_WARP;
    const int sel = l >> 3;
    const uint32_t a_base = sb + (uint32_t)quadA_off +
        (uint32_t)((((sel & 1) << 3) + (l & 7)) * STRIDE_A + ((sel >> 1) << 4));
    const uint32_t b_base = sb + SM_B + (uint32_t)qpar * (16 * STRIDE_A) +
        (uint32_t)((((sel >> 1) << 3) + (l & 7)) * STRIDE_A + ((sel & 1) << 4));

    for (int tw = blockIdx.x * N_QUAD + quad; tw < n_tiles16;
         tw += gridDim.x * N_QUAD) {
        const int m0 = tw << 4;

        // --- A tile (16 rows, quad-shared): f32 -> fp16 hi/lo split ---
#pragma unroll
        for (int ii = 0; ii < 4; ii++) {
            int row = ii * 4 + (t4 >> 5);
            int node = m0 + row;
            int kq = t4 & 31;                         // <16: hnew, >=16: h
            float4 v = make_float4(0.f, 0.f, 0.f, 0.f);
            if (node < Nn)
                v = (kq < 16) ? g_hnew4[node * 16 + kq]
                              : __ldg(&h4[node * 16 + (kq - 16)]);
            uint32_t h01 = cvth2(v.y, v.x), h23 = cvth2(v.w, v.z);
            uint32_t l01 = cvth2(v.y - f16hi_f(h01), v.x - f16lo_f(h01));
            uint32_t l23 = cvth2(v.w - f16hi_f(h23), v.z - f16lo_f(h23));
            uint32_t off = (uint32_t)quadA_off + (uint32_t)row * STRIDE_A +
                           ((uint32_t)(kq >> 1) << 4) + ((uint32_t)(kq & 1) << 3);
            *(uint2*)(smem + off)            = make_uint2(h01, h23);
            *(uint2*)(smem + off + A_HALF_W) = make_uint2(l01, l23);
        }
        QUAD_BAR(barid);

        float acc[32];
#pragma unroll
        for (int i = 0; i < 32; i++) acc[i] = 0.f;

        // ---- fp16 2-pass GEMM; gates g: 0=r 1=z 2=i_n(k<64) 3=h_n(k>=64) ----
#pragma unroll 1
        for (int s = 0; s < 4; s++) {
            uint32_t ah0, ah1, ah2, ah3, al0, al1, al2, al3;
            LDSM4(ah0, ah1, ah2, ah3, a_base + (uint32_t)s * 32);
            LDSM4(al0, al1, al2, al3, a_base + A_HALF_W + (uint32_t)s * 32);
#pragma unroll
            for (int g = 0; g < 3; g++) {             // r, z, i_n
                uint32_t b0, b1, b2, b3;
                LDSM4(b0, b1, b2, b3,
                      b_base + (uint32_t)g * (64 * STRIDE_A) + (uint32_t)s * 32);
                float* c0 = &acc[g * 8];
                float* c1 = &acc[g * 8 + 4];
                MMA16816(c0, ah0, ah1, ah2, ah3, b0, b1);
                MMA16816(c1, ah0, ah1, ah2, ah3, b2, b3);
                MMA16816(c0, al0, al1, al2, al3, b0, b1);
                MMA16816(c1, al0, al1, al2, al3, b2, b3);
            }
        }
#pragma unroll 1
        for (int s = 4; s < 8; s++) {
            uint32_t ah0, ah1, ah2, ah3, al0, al1, al2, al3;
            LDSM4(ah0, ah1, ah2, ah3, a_base + (uint32_t)s * 32);
            LDSM4(al0, al1, al2, al3, a_base + A_HALF_W + (uint32_t)s * 32);
#pragma unroll
            for (int q = 0; q < 3; q++) {
                int g = (q < 2) ? q : 3;              // r, z, h_n
                uint32_t b0, b1, b2, b3;
                LDSM4(b0, b1, b2, b3,
                      b_base + (uint32_t)g * (64 * STRIDE_A) + (uint32_t)s * 32);
                float* c0 = &acc[g * 8];
                float* c1 = &acc[g * 8 + 4];
                MMA16816(c0, ah0, ah1, ah2, ah3, b0, b1);
                MMA16816(c1, ah0, ah1, ah2, ah3, b2, b3);
                MMA16816(c0, al0, al1, al2, al3, b0, b1);
                MMA16816(c1, al0, al1, al2, al3, b2, b3);
            }
        }

        // --- Epilogue phase 1: gate math; j = 16*qpar + 8f + 2tg + b ---
#pragma unroll
        for (int f = 0; f < 2; f++) {
            const int jbase = 16 * qpar + 8 * f + 2 * tg;
            float2 br = *(const float2*)(smem + SM_BIAS + jbase * 4);
            float2 bz = *(const float2*)(smem + SM_BIAS + 256 + jbase * 4);
            float2 bi = *(const float2*)(smem + SM_BIAS + 512 + jbase * 4);
            float2 bh = *(const float2*)(smem + SM_BIAS + 768 + jbase * 4);
#pragma unroll
            for (int rs = 0; rs < 2; rs++) {
                const int node_local = r0q + rs * 8;
#pragma unroll
                for (int b = 0; b < 2; b++) {
                    int j = jbase + b;
                    int ai = f * 4 + 2 * rs + b;
                    float rp = acc[ai];
                    float zp = acc[8 + ai];
                    float ip = acc[16 + ai];
                    float hp = acc[24 + ai];
                    float rr = sigmoidf_fast(rp + (b ? br.y : br.x));
                    float zz = sigmoidf_fast(zp + (b ? bz.y : bz.x));
                    float nn = tanhf_fast(ip + (b ? bi.y : bi.x) +
                                          rr * (hp + (b ? bh.y : bh.x)));
                    int kcol = 64 + j;
                    uint32_t hoff = (uint32_t)quadA_off +
                                    (uint32_t)node_local * STRIDE_A +
                                    ((uint32_t)(kcol >> 3) << 4) +
                                    ((uint32_t)(kcol & 7) << 1);
                    uint32_t hib = *(const unsigned short*)(smem + hoff);
                    uint32_t lob = *(const unsigned short*)(smem + hoff + A_HALF_W);
                    float hv = f16lo_f(hib) + f16lo_f(lob);
                    acc[ai] = (1.f - zz) * nn + zz * hv;
                }
            }
        }
        QUAD_BAR(barid);

        // --- Phase 2: stage float2 into quad staging (XOR swizzle, 8B units) ---
#pragma unroll
        for (int f = 0; f < 2; f++) {
#pragma unroll
            for (int rs = 0; rs < 2; rs++) {
                const int row = r0q + rs * 8;
                uint32_t u8 = (uint32_t)(8 * qpar + 4 * f + tg);
                uint32_t sa = (uint32_t)quadA_off + (uint32_t)row * 256 +
                              ((u8 ^ (((uint32_t)row & 7) << 2)) << 3);
                *(float2*)(smem + sa) =
                    make_float2(acc[f * 4 + 2 * rs], acc[f * 4 + 2 * rs + 1]);
            }
        }
        QUAD_BAR(barid);

        // --- Phase 3: coalesced 16B stores (128 threads x 2 iters) ---
#pragma unroll
        for (int it = 0; it < 2; it++) {
            int idx = it * 128 + t4;
            int nl = idx >> 4, c16 = idx & 15;
            uint32_t ra = (uint32_t)quadA_off + (uint32_t)nl * 256 +
                          ((((uint32_t)(2 * c16)) ^ (((uint32_t)nl & 7) << 2)) << 3);
            float4 v = *(const float4*)(smem + ra);
            int node = m0 + nl;
            if (node < Nn) *(float4*)(out + (size_t)node * 64 + c16 * 4) = v;
        }
        QUAD_BAR(barid);
    }
}

// ---------------------------------------------------------------------------
// Launch
// ---------------------------------------------------------------------------
extern "C" void kernel_launch(void* const* d_in, const int* in_sizes, int n_in,
                              void* d_out, int out_size) {
    const float* h   = (const float*)d_in[0];
    const float* ew  = (const float*)d_in[1];
    const float* Wih = (const float*)d_in[2];
    const float* Whh = (const float*)d_in[3];
    const float* bih = (const float*)d_in[4];
    const float* bhh = (const float*)d_in[5];
    const void* srcp = d_in[6];
    const void* dstp = d_in[7];
    float* out       = (float*)d_out;

    int E  = in_sizes[1];
    int Nn = in_sizes[0] / D;
    int n_tiles16 = (Nn + 15) / 16;
    int nb = (Nn + 1023) / 1024;

    init_kernel<<<(Nn + 255) / 256, 256>>>((const unsigned long long*)srcp,
                                           (const unsigned long long*)dstp,
                                           Wih, Whh, bih, bhh, Nn);
    hist_kernel<<<(E + 255) / 256, 256>>>(dstp, E);
    scan_kernel<<<nb, 1024>>>(Nn, E, nb);
    reorder_kernel<<<(E + 255) / 256, 256>>>(srcp, dstp, ew, E);
    accum_kernel<<<(Nn * 16 + 255) / 256, 256>>>((const float4*)h, Nn);

    cudaFuncSetAttribute(gemm_gru_kernel,
                         cudaFuncAttributeMaxDynamicSharedMemorySize, SM_TOT);
    gemm_gru_kernel<<<148, 768, SM_TOT>>>((const float4*)h, out, Nn, n_tiles16);
}